// round 16
// baseline (speedup 1.0000x reference)
#include <cuda_runtime.h>
#include <cuda_fp16.h>
#include <cstdint>
#include <cstddef>

#define HW 4096
#define CD 64
// SCALE * log2(e): S' = logit*log2e, p = exp2(S')
#define PRESCALE 0.18033688011112042f
#define SW(o) ((o) ^ (((o) >> 3) & 0x70))

__device__ float g_denom[4 * HW];

// fp16 images (swizzled 128B rows): Q plain; K prescaled; Vt = (V/denom)^T.
__device__ char g_Qb[(size_t)4 * 32 * 16384];
__device__ char g_Kb[(size_t)4 * 32 * 16384];
__device__ char g_Vb[(size_t)4 * 32 * 16384];

__device__ __forceinline__ uint32_t smem_u32(const void* p) {
    uint32_t a;
    asm("{ .reg .u64 t; cvta.to.shared.u64 t, %1; cvt.u32.u64 %0, t; }" : "=r"(a) : "l"(p));
    return a;
}
__device__ __forceinline__ void cpa16(uint32_t dst, const char* src) {
    asm volatile("cp.async.cg.shared.global [%0], [%1], 16;" :: "r"(dst), "l"(src) : "memory");
}
#define CP_COMMIT() asm volatile("cp.async.commit_group;" ::: "memory")
#define CP_WAIT0()  asm volatile("cp.async.wait_group 0;" ::: "memory")
#define CP_WAIT1()  asm volatile("cp.async.wait_group 1;" ::: "memory")

__device__ __forceinline__ void ld4a(uint32_t r[4], uint32_t a) {
    asm volatile("ldmatrix.sync.aligned.m8n8.x4.shared.b16 {%0,%1,%2,%3}, [%4];"
                 : "=r"(r[0]), "=r"(r[1]), "=r"(r[2]), "=r"(r[3]) : "r"(a));
}
__device__ __forceinline__ void mma16816(float c[4], const uint32_t a[4], uint32_t b0, uint32_t b1) {
    asm volatile(
        "mma.sync.aligned.m16n8k16.row.col.f32.f16.f16.f32 "
        "{%0,%1,%2,%3}, {%4,%5,%6,%7}, {%8,%9}, {%0,%1,%2,%3};"
        : "+f"(c[0]), "+f"(c[1]), "+f"(c[2]), "+f"(c[3])
        : "r"(a[0]), "r"(a[1]), "r"(a[2]), "r"(a[3]), "r"(b0), "r"(b1));
}
__device__ __forceinline__ float ex2(float x) {
    float y; asm("ex2.approx.ftz.f32 %0, %1;" : "=f"(y) : "f"(x)); return y;
}

// 64x64 fp16 GEMM block: sacc[ntp][..] (+)= A(16 rows) x B(64 cols).
__device__ __forceinline__ void mma_block(float (&sacc)[4][8], const uint32_t (&ah)[4][4],
                                          uint32_t bbase, uint32_t t128, const uint32_t (&cx)[4]) {
#pragma unroll
    for (int t = 0; t < 4; t++)
#pragma unroll
        for (int u = 0; u < 8; u++) sacc[t][u] = 0.f;
#pragma unroll
    for (int ks = 0; ks < 4; ks++) {
        uint32_t bh[4][4];
#pragma unroll
        for (int ntp = 0; ntp < 4; ntp++) ld4a(bh[ntp], bbase + ntp * 2048 + t128 + cx[ks]);
#pragma unroll
        for (int ntp = 0; ntp < 4; ntp++) mma16816(&sacc[ntp][0], ah[ks], bh[ntp][0], bh[ntp][2]);
#pragma unroll
        for (int ntp = 0; ntp < 4; ntp++) mma16816(&sacc[ntp][4], ah[ks], bh[ntp][1], bh[ntp][3]);
    }
}

// exp via fp32 MUFU ex2 (precision-proven path).
__device__ __forceinline__ void exp_block(uint32_t (&ph)[4][4], const float (&sacc)[4][8]) {
#pragma unroll
    for (int ntp = 0; ntp < 4; ntp++) {
        __half2 h;
        h = __floats2half2_rn(ex2(sacc[ntp][0]), ex2(sacc[ntp][1])); ph[ntp][0] = *(uint32_t*)&h;
        h = __floats2half2_rn(ex2(sacc[ntp][2]), ex2(sacc[ntp][3])); ph[ntp][1] = *(uint32_t*)&h;
        h = __floats2half2_rn(ex2(sacc[ntp][4]), ex2(sacc[ntp][5])); ph[ntp][2] = *(uint32_t*)&h;
        h = __floats2half2_rn(ex2(sacc[ntp][6]), ex2(sacc[ntp][7])); ph[ntp][3] = *(uint32_t*)&h;
    }
}

__device__ __forceinline__ void pv_block(float (&oacc)[8][4], const uint32_t (&ph)[4][4],
                                         uint32_t vbase, uint32_t t128, const uint32_t (&cx)[4]) {
#pragma unroll
    for (int ks = 0; ks < 4; ks++) {
        uint32_t vh[4][4];
#pragma unroll
        for (int cp = 0; cp < 4; cp++) ld4a(vh[cp], vbase + cp * 2048 + t128 + cx[ks]);
#pragma unroll
        for (int cp = 0; cp < 4; cp++) mma16816(oacc[2 * cp],     ph[ks], vh[cp][0], vh[cp][2]);
#pragma unroll
        for (int cp = 0; cp < 4; cp++) mma16816(oacc[2 * cp + 1], ph[ks], vh[cp][1], vh[cp][3]);
    }
}

// ---------------------------------------------------------------------------
// Prep A: Q -> fp16; K -> PRESCALE*K fp16. Zeroes g_denom AND Out.
// ---------------------------------------------------------------------------
__global__ void __launch_bounds__(128)
prep_qk(const float* __restrict__ Q, const float* __restrict__ K, float* __restrict__ Out) {
    int tid = threadIdx.x;
    int s = blockIdx.x, n = blockIdx.y;
    int c = s >> 1, half = s & 1;
    size_t gb = (size_t)(n * 32 + c) * 16384;
    const float* Qg = Q + ((size_t)n * HW + s * 64) * CD;
    const float* Kg = K + ((size_t)n * HW + s * 64) * CD;

    if (s < 32) g_denom[n * HW + s * 128 + tid] = 0.0f;

    {
        size_t t = ((size_t)(n * 64 + s) * 128 + tid) * 8;
        float4 z = make_float4(0.f, 0.f, 0.f, 0.f);
#pragma unroll
        for (int i = 0; i < 8; i++) *(float4*)(Out + (t + i) * 4) = z;
    }

#pragma unroll
    for (int i = 0; i < 8; i++) {
        int lin4 = i * 128 + tid;
        int r  = lin4 >> 4;
        int c4 = (lin4 & 15) * 4;
        unsigned o = (half * 64 + r) * 128 + c4 * 2;
        unsigned sw = SW(o);
        {
            float4 v = *(const float4*)(Qg + r * CD + c4);
            __half2 h0 = __floats2half2_rn(v.x, v.y);
            __half2 h1 = __floats2half2_rn(v.z, v.w);
            *(unsigned*)(g_Qb + gb + sw)     = *(unsigned*)&h0;
            *(unsigned*)(g_Qb + gb + sw + 4) = *(unsigned*)&h1;
        }
        {
            float4 v = *(const float4*)(Kg + r * CD + c4);
            __half2 h0 = __floats2half2_rn(v.x * PRESCALE, v.y * PRESCALE);
            __half2 h1 = __floats2half2_rn(v.z * PRESCALE, v.w * PRESCALE);
            *(unsigned*)(g_Kb + gb + sw)     = *(unsigned*)&h0;
            *(unsigned*)(g_Kb + gb + sw + 4) = *(unsigned*)&h1;
        }
    }
}

// ---------------------------------------------------------------------------
// Pass 1: denom (R13-proven). CTA = 64 k rows x quarter q-range; triple-buffered
// Q ring; S(j+1) overlapped with exp-sum(j). smem 32KB.
// ---------------------------------------------------------------------------
#define Z1_K 0
#define QBUF(b) (8192 + (b) * 8192)
#define P1_SMEM 32768

__device__ __forceinline__ void p1_issue_q(uint32_t sb, int bi, int n, int cc) {
    int tid = threadIdx.x;
    const char* qs = g_Qb + (size_t)(n * 32 + (cc >> 1)) * 16384 + (cc & 1) * 8192;
    uint32_t d = sb + QBUF(bi);
#pragma unroll
    for (int i = 0; i < 4; i++) {
        int o = (i * 128 + tid) * 16;
        cpa16(d + o, qs + o);
    }
}

__device__ __forceinline__ void p1_expsum(float& ps0, float& ps1, const float (&sa)[4][8]) {
#pragma unroll
    for (int ntp = 0; ntp < 4; ntp++) {
        __half2 e01 = h2exp2(__floats2half2_rn(sa[ntp][0], sa[ntp][1]));
        __half2 e45 = h2exp2(__floats2half2_rn(sa[ntp][4], sa[ntp][5]));
        __half2 a0 = __hadd2(e01, e45);
        ps0 += __low2float(a0) + __high2float(a0);
        __half2 e23 = h2exp2(__floats2half2_rn(sa[ntp][2], sa[ntp][3]));
        __half2 e67 = h2exp2(__floats2half2_rn(sa[ntp][6], sa[ntp][7]));
        __half2 a1 = __hadd2(e23, e67);
        ps1 += __low2float(a1) + __high2float(a1);
    }
}

__device__ __forceinline__ void p1_iter(uint32_t sb, int n, int cc_issue, int bi, int bn,
                                        bool do_issue, bool do_s,
                                        float (&sa)[4][8], float (&sbk)[4][8],
                                        const uint32_t (&ah)[4][4],
                                        float& ps0, float& ps1,
                                        uint32_t t128, const uint32_t (&cx)[4]) {
    CP_WAIT0(); __syncthreads();
    if (do_issue) { p1_issue_q(sb, bi, n, cc_issue); CP_COMMIT(); }
    if (do_s) mma_block(sbk, ah, sb + QBUF(bn), t128, cx);
    p1_expsum(ps0, ps1, sa);
}

__global__ void __launch_bounds__(128, 4)
pass1_denom() {
    extern __shared__ char smem[];
    uint32_t sb = smem_u32(smem);
    int tid = threadIdx.x, w = tid >> 5, l = tid & 31;
    int kt = blockIdx.x, qs = blockIdx.y, n = blockIdx.z;

    uint32_t t128 = (uint32_t)(l & 15) * 128;
    uint32_t msk = (uint32_t)(l & 7) << 4;
    uint32_t cx[4];
#pragma unroll
    for (int ks = 0; ks < 4; ks++) cx[ks] = ((uint32_t)(ks * 32 + ((l >> 4) << 4))) ^ msk;

    int c0 = qs * 16;
    {
        const char* ksrc = g_Kb + (size_t)(n * 32 + (kt >> 1)) * 16384 + (kt & 1) * 8192;
#pragma unroll
        for (int i = 0; i < 4; i++) {
            int o = (i * 128 + tid) * 16;
            cpa16(sb + Z1_K + o, ksrc + o);
        }
        p1_issue_q(sb, 0, n, c0); CP_COMMIT();
        p1_issue_q(sb, 1, n, c0 + 1); CP_COMMIT();
        CP_WAIT1(); __syncthreads();
    }

    uint32_t ah[4][4];
#pragma unroll
    for (int ks = 0; ks < 4; ks++) ld4a(ah[ks], sb + Z1_K + w * 2048 + t128 + cx[ks]);

    float sA[4][8], sB[4][8];
    float ps0 = 0.f, ps1 = 0.f;
    mma_block(sA, ah, sb + QBUF(0), t128, cx);

#pragma unroll 1
    for (int m = 0; m < 2; m++) {
        int j0 = m * 6;
        p1_iter(sb, n, c0 + j0 + 2, 2, 1, true, true, sA, sB, ah, ps0, ps1, t128, cx);
        p1_iter(sb, n, c0 + j0 + 3, 0, 2, true, true, sB, sA, ah, ps0, ps1, t128, cx);
        p1_iter(sb, n, c0 + j0 + 4, 1, 0, true, true, sA, sB, ah, ps0, ps1, t128, cx);
        p1_iter(sb, n, c0 + j0 + 5, 2, 1, true, true, sB, sA, ah, ps0, ps1, t128, cx);
        p1_iter(sb, n, c0 + j0 + 6, 0, 2, true, true, sA, sB, ah, ps0, ps1, t128, cx);
        p1_iter(sb, n, c0 + j0 + 7, 1, 0, true, true, sB, sA, ah, ps0, ps1, t128, cx);
    }
    p1_iter(sb, n, c0 + 14, 2, 1, true,  true,  sA, sB, ah, ps0, ps1, t128, cx);
    p1_iter(sb, n, c0 + 15, 0, 2, true,  true,  sB, sA, ah, ps0, ps1, t128, cx);
    p1_iter(sb, n, 0,       0, 0, false, true,  sA, sB, ah, ps0, ps1, t128, cx);
    p1_iter(sb, n, 0,       0, 0, false, false, sB, sA, ah, ps0, ps1, t128, cx);

    ps0 += __shfl_xor_sync(0xFFFFFFFFu, ps0, 1);
    ps0 += __shfl_xor_sync(0xFFFFFFFFu, ps0, 2);
    ps1 += __shfl_xor_sync(0xFFFFFFFFu, ps1, 1);
    ps1 += __shfl_xor_sync(0xFFFFFFFFu, ps1, 2);
    if ((l & 3) == 0) {
        int r = l >> 2;
        atomicAdd(&g_denom[n * HW + kt * 64 + w * 16 + r],     ps0);
        atomicAdd(&g_denom[n * HW + kt * 64 + w * 16 + 8 + r], ps1);
    }
}

// ---------------------------------------------------------------------------
// Prep B: Vt = (V/denom)^T, fp16.
// ---------------------------------------------------------------------------
__global__ void __launch_bounds__(128)
prep_v(const float* __restrict__ V) {
    __shared__ char sm[8192];
    int tid = threadIdx.x;
    int s = blockIdx.x, n = blockIdx.y;
    int c = s >> 1, h = s & 1;

    const float* g = V + ((size_t)n * HW + s * 64) * CD;
    const float* dn = g_denom + n * HW + s * 64;
#pragma unroll
    for (int i = 0; i < 8; i++) {
        int lin4 = i * 128 + tid;
        int k  = lin4 >> 4;
        int c4 = (lin4 & 15) * 4;
        float di = __frcp_rn(dn[k]);
        float4 v = *(const float4*)(g + k * CD + c4);
        float vv[4] = {v.x * di, v.y * di, v.z * di, v.w * di};
#pragma unroll
        for (int j = 0; j < 4; j++) {
            unsigned o = (c4 + j) * 128 + k * 2;
            *(__half*)(sm + SW(o)) = __float2half_rn(vv[j]);
        }
    }
    __syncthreads();

    size_t gb = (size_t)(n * 32 + c) * 16384 + h * 8192;
#pragma unroll
    for (int i = 0; i < 4; i++) {
        int o = (i * 128 + tid) * 16;
        *(float4*)(g_Vb + gb + o) = *(const float4*)(sm + o);
    }
}

// ---------------------------------------------------------------------------
// Pass 2 v3: CTA = 128 q rows (4 warps x 2 rowsets of 16), 128 threads,
// 2 CTAs/SM. grid (32 q-tiles, 2 k-halves, N) = 256 CTAs. 32 chunks/CTA,
// TRIPLE-buffered KV; rowset-staggered pipeline:
//   enter iter j with sacc_r0(j);
//   A: S_r1(j) || exp_r0(j);  B: PV_r0(j) || exp_r1(j);  C: S_r0(j+1) || PV_r1(j)
// Epilogue atomicAdd (exactly 2 contributors/element -> deterministic).
// smem: Q 16KB + 3 x 16KB = 64KB.
// ---------------------------------------------------------------------------
#define Q2_OFF 0
#define KV2BUF(b) (16384 + (b) * 16384)   /* K 8KB, V at +8192 */
#define P2_SMEM 65536

__device__ __forceinline__ void p2_issue_kv(uint32_t sb, int bi, int n, int cc) {
    int tid = threadIdx.x;
    size_t cb = (size_t)(n * 32 + (cc >> 1)) * 16384 + (cc & 1) * 8192;
    const char* ksrc = g_Kb + cb;
    const char* vsrc = g_Vb + cb;
    uint32_t d = sb + KV2BUF(bi);
#pragma unroll
    for (int i = 0; i < 4; i++) {
        int o = (i * 128 + tid) * 16;
        cpa16(d + o,        ksrc + o);
        cpa16(d + 8192 + o, vsrc + o);
    }
}

__global__ void __launch_bounds__(128, 2)
pass2_out(float* __restrict__ Out) {
    extern __shared__ char smem[];
    uint32_t sb = smem_u32(smem);
    int tid = threadIdx.x, w = tid >> 5, l = tid & 31;
    int qt = blockIdx.x, kh = blockIdx.y, n = blockIdx.z;
    int c0 = kh * 32;

    uint32_t t128 = (uint32_t)(l & 15) * 128;
    uint32_t msk = (uint32_t)(l & 7) << 4;
    uint32_t cx[4];
#pragma unroll
    for (int ks = 0; ks < 4; ks++) cx[ks] = ((uint32_t)(ks * 32 + ((l >> 4) << 4))) ^ msk;

    // prologue: Q tile (16KB) + KV chunk0 as group0; KV chunk1 as group1
    {
        const char* qsrc = g_Qb + (size_t)(n * 32 + qt) * 16384;
#pragma unroll
        for (int i = 0; i < 8; i++) {
            int o = (i * 128 + tid) * 16;
            cpa16(sb + Q2_OFF + o, qsrc + o);
        }
        p2_issue_kv(sb, 0, n, c0);
        CP_COMMIT();
        p2_issue_kv(sb, 1, n, c0 + 1);
        CP_COMMIT();
        CP_WAIT1(); __syncthreads();   // Q + chunk0 ready
    }

    uint32_t qh[2][4][4];
#pragma unroll
    for (int r = 0; r < 2; r++)
#pragma unroll
        for (int ks = 0; ks < 4; ks++)
            ld4a(qh[r][ks], sb + Q2_OFF + (w * 32 + r * 16) * 128 + t128 + cx[ks]);

    float oacc0[8][4], oacc1[8][4];
#pragma unroll
    for (int i = 0; i < 8; i++)
#pragma unroll
        for (int j = 0; j < 4; j++) { oacc0[i][j] = 0.f; oacc1[i][j] = 0.f; }

    float s0[4][8], s1[4][8];
    uint32_t p0[4][4], p1[4][4];

    mma_block(s0, qh[0], sb + KV2BUF(0), t128, cx);   // S_r0(chunk0)

    int cur = 0, nxt = 1, iss = 2;
#pragma unroll 1
    for (int j = 0; j < 30; j++) {
        CP_WAIT0(); __syncthreads();
        p2_issue_kv(sb, iss, n, c0 + j + 2); CP_COMMIT();

        uint32_t kb = sb + KV2BUF(cur);
        uint32_t vb = kb + 8192;
        // A: S_r1(j) || exp_r0(j)
        mma_block(s1, qh[1], kb, t128, cx);
        exp_block(p0, s0);
        // B: PV_r0(j) || exp_r1(j)
        pv_block(oacc0, p0, vb, t128, cx);
        exp_block(p1, s1);
        // C: S_r0(j+1) || PV_r1(j)
        mma_block(s0, qh[0], sb + KV2BUF(nxt), t128, cx);
        pv_block(oacc1, p1, vb, t128, cx);

        int t = cur; cur = nxt; nxt = iss; iss = t;
    }
    // j = 30: no issue; still compute S_r0(31). cur=0, nxt=1 (30%3==0)
    {
        CP_WAIT0(); __syncthreads();
        uint32_t kb = sb + KV2BUF(cur);
        uint32_t vb = kb + 8192;
        mma_block(s1, qh[1], kb, t128, cx);
        exp_block(p0, s0);
        pv_block(oacc0, p0, vb, t128, cx);
        exp_block(p1, s1);
        mma_block(s0, qh[0], sb + KV2BUF(nxt), t128, cx);
        pv_block(oacc1, p1, vb, t128, cx);
        cur = nxt;
    }
    // j = 31: final chunk, no S_r0(next)
    {
        uint32_t kb = sb + KV2BUF(cur);
        uint32_t vb = kb + 8192;
        mma_block(s1, qh[1], kb, t128, cx);
        exp_block(p0, s0);
        pv_block(oacc0, p0, vb, t128, cx);
        exp_block(p1, s1);
        pv_block(oacc1, p1, vb, t128, cx);
    }

    // epilogue: atomicAdd partial O (2 contributors/element, deterministic)
#pragma unroll
    for (int r = 0; r < 2; r++) {
        float (*oa)[4] = (r == 0) ? oacc0 : oacc1;
        int qr = qt * 128 + w * 32 + r * 16 + (l >> 2);
        float* o0 = Out + ((size_t)n * HW + qr) * CD;
        float* o1 = o0 + 8 * CD;
#pragma unroll
        for (int nt = 0; nt < 8; nt++) {
            int cc = nt * 8 + 2 * (l & 3);
            atomicAdd(o0 + cc,     oa[nt][0]);
            atomicAdd(o0 + cc + 1, oa[nt][1]);
            atomicAdd(o1 + cc,     oa[nt][2]);
            atomicAdd(o1 + cc + 1, oa[nt][3]);
        }
    }
}

// ---------------------------------------------------------------------------
extern "C" void kernel_launch(void* const* d_in, const int* in_sizes, int n_in,
                              void* d_out, int out_size) {
    const float* Q = (const float*)d_in[0];
    const float* K = (const float*)d_in[1];
    const float* V = (const float*)d_in[2];
    float* Out = (float*)d_out;
    const int N = in_sizes[0] / (HW * CD);  // = 4

    cudaFuncSetAttribute(pass1_denom, cudaFuncAttributeMaxDynamicSharedMemorySize, P1_SMEM);
    cudaFuncSetAttribute(pass2_out,   cudaFuncAttributeMaxDynamicSharedMemorySize, P2_SMEM);

    prep_qk<<<dim3(64, N), 128>>>(Q, K, Out);
    pass1_denom<<<dim3(64, 4, N), 128, P1_SMEM>>>();
    prep_v<<<dim3(64, N), 128>>>(V);
    pass2_out<<<dim3(32, 2, N), 128, P2_SMEM>>>(Out);
}

// round 17
// speedup vs baseline: 1.0401x; 1.0401x over previous
#include <cuda_runtime.h>
#include <cuda_fp16.h>
#include <cstdint>
#include <cstddef>

#define HW 4096
#define CD 64
// SCALE * log2(e): S' = logit*log2e, p = exp2(S')
#define PRESCALE 0.18033688011112042f
#define SW(o) ((o) ^ (((o) >> 3) & 0x70))

__device__ float g_denom[4 * HW];

// fp16 images (swizzled 128B rows): Q plain; K prescaled; Vt = (V/denom)^T.
__device__ char g_Qb[(size_t)4 * 32 * 16384];
__device__ char g_Kb[(size_t)4 * 32 * 16384];
__device__ char g_Vb[(size_t)4 * 32 * 16384];

__device__ __forceinline__ uint32_t smem_u32(const void* p) {
    uint32_t a;
    asm("{ .reg .u64 t; cvta.to.shared.u64 t, %1; cvt.u32.u64 %0, t; }" : "=r"(a) : "l"(p));
    return a;
}
__device__ __forceinline__ void cpa16(uint32_t dst, const char* src) {
    asm volatile("cp.async.cg.shared.global [%0], [%1], 16;" :: "r"(dst), "l"(src) : "memory");
}
#define CP_COMMIT() asm volatile("cp.async.commit_group;" ::: "memory")
#define CP_WAIT0()  asm volatile("cp.async.wait_group 0;" ::: "memory")
#define CP_WAIT1()  asm volatile("cp.async.wait_group 1;" ::: "memory")

__device__ __forceinline__ void ld4a(uint32_t r[4], uint32_t a) {
    asm volatile("ldmatrix.sync.aligned.m8n8.x4.shared.b16 {%0,%1,%2,%3}, [%4];"
                 : "=r"(r[0]), "=r"(r[1]), "=r"(r[2]), "=r"(r[3]) : "r"(a));
}
__device__ __forceinline__ void mma16816(float c[4], const uint32_t a[4], uint32_t b0, uint32_t b1) {
    asm volatile(
        "mma.sync.aligned.m16n8k16.row.col.f32.f16.f16.f32 "
        "{%0,%1,%2,%3}, {%4,%5,%6,%7}, {%8,%9}, {%0,%1,%2,%3};"
        : "+f"(c[0]), "+f"(c[1]), "+f"(c[2]), "+f"(c[3])
        : "r"(a[0]), "r"(a[1]), "r"(a[2]), "r"(a[3]), "r"(b0), "r"(b1));
}
__device__ __forceinline__ float ex2(float x) {
    float y; asm("ex2.approx.ftz.f32 %0, %1;" : "=f"(y) : "f"(x)); return y;
}

// 64x64 fp16 GEMM block: sacc[ntp][..] = A(16 rows/warp) x B(64 cols).
__device__ __forceinline__ void mma_block(float (&sacc)[4][8], const uint32_t (&ah)[4][4],
                                          uint32_t bbase, uint32_t t128, const uint32_t (&cx)[4]) {
#pragma unroll
    for (int t = 0; t < 4; t++)
#pragma unroll
        for (int u = 0; u < 8; u++) sacc[t][u] = 0.f;
#pragma unroll
    for (int ks = 0; ks < 4; ks++) {
        uint32_t bh[4][4];
#pragma unroll
        for (int ntp = 0; ntp < 4; ntp++) ld4a(bh[ntp], bbase + ntp * 2048 + t128 + cx[ks]);
#pragma unroll
        for (int ntp = 0; ntp < 4; ntp++) mma16816(&sacc[ntp][0], ah[ks], bh[ntp][0], bh[ntp][2]);
#pragma unroll
        for (int ntp = 0; ntp < 4; ntp++) mma16816(&sacc[ntp][4], ah[ks], bh[ntp][1], bh[ntp][3]);
    }
}

// exp via fp32 MUFU ex2 (precision-proven path).
__device__ __forceinline__ void exp_block(uint32_t (&ph)[4][4], const float (&sacc)[4][8]) {
#pragma unroll
    for (int ntp = 0; ntp < 4; ntp++) {
        __half2 h;
        h = __floats2half2_rn(ex2(sacc[ntp][0]), ex2(sacc[ntp][1])); ph[ntp][0] = *(uint32_t*)&h;
        h = __floats2half2_rn(ex2(sacc[ntp][2]), ex2(sacc[ntp][3])); ph[ntp][1] = *(uint32_t*)&h;
        h = __floats2half2_rn(ex2(sacc[ntp][4]), ex2(sacc[ntp][5])); ph[ntp][2] = *(uint32_t*)&h;
        h = __floats2half2_rn(ex2(sacc[ntp][6]), ex2(sacc[ntp][7])); ph[ntp][3] = *(uint32_t*)&h;
    }
}

__device__ __forceinline__ void pv_block(float (&oacc)[8][4], const uint32_t (&ph)[4][4],
                                         uint32_t vbase, uint32_t t128, const uint32_t (&cx)[4]) {
#pragma unroll
    for (int ks = 0; ks < 4; ks++) {
        uint32_t vh[4][4];
#pragma unroll
        for (int cp = 0; cp < 4; cp++) ld4a(vh[cp], vbase + cp * 2048 + t128 + cx[ks]);
#pragma unroll
        for (int cp = 0; cp < 4; cp++) mma16816(oacc[2 * cp],     ph[ks], vh[cp][0], vh[cp][2]);
#pragma unroll
        for (int cp = 0; cp < 4; cp++) mma16816(oacc[2 * cp + 1], ph[ks], vh[cp][1], vh[cp][3]);
    }
}

// ---------------------------------------------------------------------------
// Prep A: Q -> fp16; K -> PRESCALE*K fp16. Zeroes g_denom.
// ---------------------------------------------------------------------------
__global__ void __launch_bounds__(128)
prep_qk(const float* __restrict__ Q, const float* __restrict__ K) {
    int tid = threadIdx.x;
    int s = blockIdx.x, n = blockIdx.y;
    int c = s >> 1, half = s & 1;
    size_t gb = (size_t)(n * 32 + c) * 16384;
    const float* Qg = Q + ((size_t)n * HW + s * 64) * CD;
    const float* Kg = K + ((size_t)n * HW + s * 64) * CD;

    if (s < 32) g_denom[n * HW + s * 128 + tid] = 0.0f;

#pragma unroll
    for (int i = 0; i < 8; i++) {
        int lin4 = i * 128 + tid;
        int r  = lin4 >> 4;
        int c4 = (lin4 & 15) * 4;
        unsigned o = (half * 64 + r) * 128 + c4 * 2;
        unsigned sw = SW(o);
        {
            float4 v = *(const float4*)(Qg + r * CD + c4);
            __half2 h0 = __floats2half2_rn(v.x, v.y);
            __half2 h1 = __floats2half2_rn(v.z, v.w);
            *(unsigned*)(g_Qb + gb + sw)     = *(unsigned*)&h0;
            *(unsigned*)(g_Qb + gb + sw + 4) = *(unsigned*)&h1;
        }
        {
            float4 v = *(const float4*)(Kg + r * CD + c4);
            __half2 h0 = __floats2half2_rn(v.x * PRESCALE, v.y * PRESCALE);
            __half2 h1 = __floats2half2_rn(v.z * PRESCALE, v.w * PRESCALE);
            *(unsigned*)(g_Kb + gb + sw)     = *(unsigned*)&h0;
            *(unsigned*)(g_Kb + gb + sw + 4) = *(unsigned*)&h1;
        }
    }
}

// ---------------------------------------------------------------------------
// Pass 1: denom. CTA = 64 k rows x quarter q-range. Q triple-buffered ring;
// S(j+1) overlapped with exp-sum(j). smem: K 8KB + 3 x Q 8KB = 32KB.
// ---------------------------------------------------------------------------
#define Z1_K 0
#define QBUF(b) (8192 + (b) * 8192)
#define P1_SMEM 32768

__device__ __forceinline__ void p1_issue_q(uint32_t sb, int bi, int n, int cc) {
    int tid = threadIdx.x;
    const char* qs = g_Qb + (size_t)(n * 32 + (cc >> 1)) * 16384 + (cc & 1) * 8192;
    uint32_t d = sb + QBUF(bi);
#pragma unroll
    for (int i = 0; i < 4; i++) {
        int o = (i * 128 + tid) * 16;
        cpa16(d + o, qs + o);
    }
}

__device__ __forceinline__ void p1_expsum(float& ps0, float& ps1, const float (&sa)[4][8]) {
#pragma unroll
    for (int ntp = 0; ntp < 4; ntp++) {
        __half2 e01 = h2exp2(__floats2half2_rn(sa[ntp][0], sa[ntp][1]));
        __half2 e45 = h2exp2(__floats2half2_rn(sa[ntp][4], sa[ntp][5]));
        __half2 a0 = __hadd2(e01, e45);
        ps0 += __low2float(a0) + __high2float(a0);
        __half2 e23 = h2exp2(__floats2half2_rn(sa[ntp][2], sa[ntp][3]));
        __half2 e67 = h2exp2(__floats2half2_rn(sa[ntp][6], sa[ntp][7]));
        __half2 a1 = __hadd2(e23, e67);
        ps1 += __low2float(a1) + __high2float(a1);
    }
}

__device__ __forceinline__ void p1_iter(uint32_t sb, int n, int cc_issue, int bi, int bn,
                                        bool do_issue, bool do_s,
                                        float (&sa)[4][8], float (&sbk)[4][8],
                                        const uint32_t (&ah)[4][4],
                                        float& ps0, float& ps1,
                                        uint32_t t128, const uint32_t (&cx)[4]) {
    CP_WAIT0(); __syncthreads();
    if (do_issue) { p1_issue_q(sb, bi, n, cc_issue); CP_COMMIT(); }
    if (do_s) mma_block(sbk, ah, sb + QBUF(bn), t128, cx);   // tensor: S(j+1)
    p1_expsum(ps0, ps1, sa);                                  // mufu: exp(j), overlaps
}

__global__ void __launch_bounds__(128, 4)
pass1_denom() {
    extern __shared__ char smem[];
    uint32_t sb = smem_u32(smem);
    int tid = threadIdx.x, w = tid >> 5, l = tid & 31;
    int kt = blockIdx.x, qs = blockIdx.y, n = blockIdx.z;

    uint32_t t128 = (uint32_t)(l & 15) * 128;
    uint32_t msk = (uint32_t)(l & 7) << 4;
    uint32_t cx[4];
#pragma unroll
    for (int ks = 0; ks < 4; ks++) cx[ks] = ((uint32_t)(ks * 32 + ((l >> 4) << 4))) ^ msk;

    int c0 = qs * 16;
    {
        const char* ksrc = g_Kb + (size_t)(n * 32 + (kt >> 1)) * 16384 + (kt & 1) * 8192;
#pragma unroll
        for (int i = 0; i < 4; i++) {
            int o = (i * 128 + tid) * 16;
            cpa16(sb + Z1_K + o, ksrc + o);
        }
        p1_issue_q(sb, 0, n, c0); CP_COMMIT();
        p1_issue_q(sb, 1, n, c0 + 1); CP_COMMIT();
        CP_WAIT1(); __syncthreads();
    }

    uint32_t ah[4][4];
#pragma unroll
    for (int ks = 0; ks < 4; ks++) ld4a(ah[ks], sb + Z1_K + w * 2048 + t128 + cx[ks]);

    float sA[4][8], sB[4][8];
    float ps0 = 0.f, ps1 = 0.f;
    mma_block(sA, ah, sb + QBUF(0), t128, cx);   // S(0)

#pragma unroll 1
    for (int m = 0; m < 2; m++) {
        int j0 = m * 6;
        p1_iter(sb, n, c0 + j0 + 2, 2, 1, true, true, sA, sB, ah, ps0, ps1, t128, cx);
        p1_iter(sb, n, c0 + j0 + 3, 0, 2, true, true, sB, sA, ah, ps0, ps1, t128, cx);
        p1_iter(sb, n, c0 + j0 + 4, 1, 0, true, true, sA, sB, ah, ps0, ps1, t128, cx);
        p1_iter(sb, n, c0 + j0 + 5, 2, 1, true, true, sB, sA, ah, ps0, ps1, t128, cx);
        p1_iter(sb, n, c0 + j0 + 6, 0, 2, true, true, sA, sB, ah, ps0, ps1, t128, cx);
        p1_iter(sb, n, c0 + j0 + 7, 1, 0, true, true, sB, sA, ah, ps0, ps1, t128, cx);
    }
    p1_iter(sb, n, c0 + 14, 2, 1, true,  true,  sA, sB, ah, ps0, ps1, t128, cx);
    p1_iter(sb, n, c0 + 15, 0, 2, true,  true,  sB, sA, ah, ps0, ps1, t128, cx);
    p1_iter(sb, n, 0,       0, 0, false, true,  sA, sB, ah, ps0, ps1, t128, cx);
    p1_iter(sb, n, 0,       0, 0, false, false, sB, sA, ah, ps0, ps1, t128, cx);

    ps0 += __shfl_xor_sync(0xFFFFFFFFu, ps0, 1);
    ps0 += __shfl_xor_sync(0xFFFFFFFFu, ps0, 2);
    ps1 += __shfl_xor_sync(0xFFFFFFFFu, ps1, 1);
    ps1 += __shfl_xor_sync(0xFFFFFFFFu, ps1, 2);
    if ((l & 3) == 0) {
        int r = l >> 2;
        atomicAdd(&g_denom[n * HW + kt * 64 + w * 16 + r],     ps0);
        atomicAdd(&g_denom[n * HW + kt * 64 + w * 16 + 8 + r], ps1);
    }
}

// ---------------------------------------------------------------------------
// Prep B: Vt = (V/denom)^T, fp16.
// ---------------------------------------------------------------------------
__global__ void __launch_bounds__(128)
prep_v(const float* __restrict__ V) {
    __shared__ char sm[8192];
    int tid = threadIdx.x;
    int s = blockIdx.x, n = blockIdx.y;
    int c = s >> 1, h = s & 1;

    const float* g = V + ((size_t)n * HW + s * 64) * CD;
    const float* dn = g_denom + n * HW + s * 64;
#pragma unroll
    for (int i = 0; i < 8; i++) {
        int lin4 = i * 128 + tid;
        int k  = lin4 >> 4;
        int c4 = (lin4 & 15) * 4;
        float di = __frcp_rn(dn[k]);
        float4 v = *(const float4*)(g + k * CD + c4);
        float vv[4] = {v.x * di, v.y * di, v.z * di, v.w * di};
#pragma unroll
        for (int j = 0; j < 4; j++) {
            unsigned o = (c4 + j) * 128 + k * 2;
            *(__half*)(sm + SW(o)) = __float2half_rn(vv[j]);
        }
    }
    __syncthreads();

    size_t gb = (size_t)(n * 32 + c) * 16384 + h * 8192;
#pragma unroll
    for (int i = 0; i < 4; i++) {
        int o = (i * 128 + tid) * 16;
        *(float4*)(g_Vb + gb + o) = *(const float4*)(sm + o);
    }
}

// ---------------------------------------------------------------------------
// Pass 2: CTA = 64 q rows, 128 threads, 4 CTAs/SM (register-capped).
// 64 k-chunks, triple-buffered KV ring; per iter: S(j+1) interleaved with
// exp(j), then PV(j). smem: Q 8KB + 3 x 16KB = 56KB.
// ---------------------------------------------------------------------------
#define Q_OFF 0
#define KVBUF(b) (8192 + (b) * 16384)   /* K 8KB, V at +8192 */
#define P2_SMEM 57344

__device__ __forceinline__ void p2_issue_kv(uint32_t sb, int bi, int n, int cc) {
    int tid = threadIdx.x;
    size_t cb = (size_t)(n * 32 + (cc >> 1)) * 16384 + (cc & 1) * 8192;
    const char* ksrc = g_Kb + cb;
    const char* vsrc = g_Vb + cb;
    uint32_t d = sb + KVBUF(bi);
#pragma unroll
    for (int i = 0; i < 4; i++) {
        int o = (i * 128 + tid) * 16;
        cpa16(d + o,        ksrc + o);
        cpa16(d + 8192 + o, vsrc + o);
    }
}

__device__ __forceinline__ void p2_iter(uint32_t sb, int n, int cc_issue,
                                        int bi, int bn, int bc, bool do_issue, bool do_s,
                                        float (&sa)[4][8], float (&sbk)[4][8],
                                        uint32_t (&ph)[4][4], float (&oacc)[8][4],
                                        const uint32_t (&qh)[4][4],
                                        uint32_t t128, const uint32_t (&cx)[4]) {
    CP_WAIT0(); __syncthreads();
    if (do_issue) { p2_issue_kv(sb, bi, n, cc_issue); CP_COMMIT(); }
    if (do_s) mma_block(sbk, qh, sb + KVBUF(bn), t128, cx);     // tensor: S(j+1)
    exp_block(ph, sa);                                           // mufu: exp(j)
    pv_block(oacc, ph, sb + KVBUF(bc) + 8192, t128, cx);         // tensor: PV(j)
}

__global__ void __launch_bounds__(128, 4)
pass2_out(float* __restrict__ Out) {
    extern __shared__ char smem[];
    uint32_t sb = smem_u32(smem);
    int tid = threadIdx.x, w = tid >> 5, l = tid & 31;
    int qt = blockIdx.x, n = blockIdx.y;

    uint32_t t128 = (uint32_t)(l & 15) * 128;
    uint32_t msk = (uint32_t)(l & 7) << 4;
    uint32_t cx[4];
#pragma unroll
    for (int ks = 0; ks < 4; ks++) cx[ks] = ((uint32_t)(ks * 32 + ((l >> 4) << 4))) ^ msk;

    {
        const char* qsrc = g_Qb + (size_t)(n * 32 + (qt >> 1)) * 16384 + (qt & 1) * 8192;
#pragma unroll
        for (int i = 0; i < 4; i++) {
            int o = (i * 128 + tid) * 16;
            cpa16(sb + Q_OFF + o, qsrc + o);
        }
        p2_issue_kv(sb, 0, n, 0); CP_COMMIT();
        p2_issue_kv(sb, 1, n, 1); CP_COMMIT();
        CP_WAIT1(); __syncthreads();
    }

    uint32_t qh[4][4];
#pragma unroll
    for (int ks = 0; ks < 4; ks++) ld4a(qh[ks], sb + Q_OFF + w * 2048 + t128 + cx[ks]);

    float oacc[8][4];
#pragma unroll
    for (int i = 0; i < 8; i++)
#pragma unroll
        for (int j = 0; j < 4; j++) oacc[i][j] = 0.f;

    float sA[4][8], sB[4][8];
    uint32_t ph[4][4];
    mma_block(sA, qh, sb + KVBUF(0), t128, cx);   // S(0)

#pragma unroll 1
    for (int m = 0; m < 10; m++) {
        int j0 = m * 6;
        p2_iter(sb, n, j0 + 2, 2, 1, 0, true, true, sA, sB, ph, oacc, qh, t128, cx);
        p2_iter(sb, n, j0 + 3, 0, 2, 1, true, true, sB, sA, ph, oacc, qh, t128, cx);
        p2_iter(sb, n, j0 + 4, 1, 0, 2, true, true, sA, sB, ph, oacc, qh, t128, cx);
        p2_iter(sb, n, j0 + 5, 2, 1, 0, true, true, sB, sA, ph, oacc, qh, t128, cx);
        p2_iter(sb, n, j0 + 6, 0, 2, 1, true, true, sA, sB, ph, oacc, qh, t128, cx);
        p2_iter(sb, n, j0 + 7, 1, 0, 2, true, true, sB, sA, ph, oacc, qh, t128, cx);
    }
    p2_iter(sb, n, 62, 2, 1, 0, true,  true,  sA, sB, ph, oacc, qh, t128, cx);
    p2_iter(sb, n, 63, 0, 2, 1, true,  true,  sB, sA, ph, oacc, qh, t128, cx);
    p2_iter(sb, n, 0,  0, 0, 2, false, true,  sA, sB, ph, oacc, qh, t128, cx);
    p2_iter(sb, n, 0,  0, 0, 0, false, false, sB, sA, ph, oacc, qh, t128, cx);

    {
        int qr = qt * 64 + w * 16 + (l >> 2);
        float* o0 = Out + ((size_t)n * HW + qr) * CD;
        float* o1 = o0 + 8 * CD;
#pragma unroll
        for (int nt = 0; nt < 8; nt++) {
            int c0 = nt * 8 + 2 * (l & 3);
            *(float2*)(o0 + c0) = make_float2(oacc[nt][0], oacc[nt][1]);
            *(float2*)(o1 + c0) = make_float2(oacc[nt][2], oacc[nt][3]);
        }
    }
}

// ---------------------------------------------------------------------------
extern "C" void kernel_launch(void* const* d_in, const int* in_sizes, int n_in,
                              void* d_out, int out_size) {
    const float* Q = (const float*)d_in[0];
    const float* K = (const float*)d_in[1];
    const float* V = (const float*)d_in[2];
    float* Out = (float*)d_out;
    const int N = in_sizes[0] / (HW * CD);  // = 4

    cudaFuncSetAttribute(pass1_denom, cudaFuncAttributeMaxDynamicSharedMemorySize, P1_SMEM);
    cudaFuncSetAttribute(pass2_out,   cudaFuncAttributeMaxDynamicSharedMemorySize, P2_SMEM);

    prep_qk<<<dim3(64, N), 128>>>(Q, K);
    pass1_denom<<<dim3(64, 4, N), 128, P1_SMEM>>>();
    prep_v<<<dim3(64, N), 128>>>(V);
    pass2_out<<<dim3(64, N), 128, P2_SMEM>>>(Out);
}